// round 4
// baseline (speedup 1.0000x reference)
#include <cuda_runtime.h>
#include <cuda_bf16.h>
#include <cstdint>

// ---------------------------------------------------------------------------
// R=4, B=256, N=200, NF=5, H=50, OUT=2. grid g = r*256 + b. One CTA per graph.
//
// Per graph:
//   deg[n]  = 1 + sum_m adj[n,m];  dinv[n] = rsqrt(deg[n])
//   zd[m,f] = dinv[m] * (x @ W1)[m,f]
//   D[n,f]  = sum_m A[n,m] * zd[m,f]            (A = adj + I, exact in bf16)
//   q[m]    = dinv[m] * sum_f silu(dinv[m]*D[m,f] + b1[f]) * (W2@W3)[f]
//   e       = sum_n dinv[n] * (A[n,:] . q)
// out[b] = sum_r nu[b,r] * (e(r,b) + 200*(b2.W3 + b3))
//
// GEMM engine: warp-level mma.sync m16n8k16 bf16 (sm_100 baseline; tcgen05 is
// sm_100a-only and this build targets plain sm_100).
// A operand [208x208] bf16 row-major, row stride 432 B (conflict-free ldmatrix).
// B operand = zd^T [56 f][208 m] bf16 row-major (= col-major B), hi + lo split
// accumulated into the same fp32 C fragments (A exact => order-free).
// D store: scalar st.shared.f32 only — row stride 228 B is 4-mod-8, so v2
// stores trap on odd rows (the Round-3 bug).
// ---------------------------------------------------------------------------

static constexpr int STRA = 432;                    // A row stride bytes (216 bf16)
static constexpr int STRD = 228;                    // D row stride bytes (57 f32)

static constexpr int SM_DINV = 0;                   // 256 f32
static constexpr int SM_Q    = 1024;                // 256 f32
static constexpr int SM_X    = 2048;                // 1000 f32
static constexpr int SM_W1   = 6048;                // 250 f32
static constexpr int SM_W    = 7048;                // 50 f32 (W2@W3)
static constexpr int SM_B1   = 7248;                // 50 f32
static constexpr int SM_EP   = 7456;                // 8 f32
static constexpr int SM_A    = 7552;                // 208*432 = 89856
static constexpr int SM_ZH   = SM_A  + 208 * STRA;  // 97408:  56*432 = 24192
static constexpr int SM_ZL   = SM_ZH + 56 * STRA;   // 121600: 56*432 = 24192
static constexpr int SM_D    = SM_ZL + 56 * STRA;   // 145792: 208*228 = 47424
static constexpr int SM_TOTAL= SM_D  + 208 * STRD;  // 193216 bytes

__device__ float g_e[1024];   // per-graph energy (deterministic combine kernel)

// ---------------------------------------------------------------------------
static __device__ __forceinline__ uint32_t smem_u32(const void* p) {
    uint32_t a;
    asm("{ .reg .u64 t; cvta.to.shared.u64 t, %1; cvt.u32.u64 %0, t; }" : "=r"(a) : "l"(p));
    return a;
}
static __device__ __forceinline__ void ldsm_x4(uint32_t& r0, uint32_t& r1,
                                               uint32_t& r2, uint32_t& r3, uint32_t a) {
    asm volatile("ldmatrix.sync.aligned.m8n8.x4.shared.b16 {%0,%1,%2,%3}, [%4];"
                 : "=r"(r0), "=r"(r1), "=r"(r2), "=r"(r3) : "r"(a));
}
static __device__ __forceinline__ void ldsm_x2(uint32_t& r0, uint32_t& r1, uint32_t a) {
    asm volatile("ldmatrix.sync.aligned.m8n8.x2.shared.b16 {%0,%1}, [%2];"
                 : "=r"(r0), "=r"(r1) : "r"(a));
}
static __device__ __forceinline__ void mma16816(float* c,
                                                uint32_t a0, uint32_t a1, uint32_t a2, uint32_t a3,
                                                uint32_t b0, uint32_t b1) {
    asm volatile("mma.sync.aligned.m16n8k16.row.col.f32.bf16.bf16.f32 "
                 "{%0,%1,%2,%3}, {%4,%5,%6,%7}, {%8,%9}, {%0,%1,%2,%3};"
                 : "+f"(c[0]), "+f"(c[1]), "+f"(c[2]), "+f"(c[3])
                 : "r"(a0), "r"(a1), "r"(a2), "r"(a3), "r"(b0), "r"(b1));
}

// ---------------------------------------------------------------------------
__global__ void __launch_bounds__(256, 1) gnn_main(
    const float* __restrict__ x,   // [R,B,200,5]
    const int*   __restrict__ adj, // [R,B,200,200]
    const float* __restrict__ W1,  // [5,50]
    const float* __restrict__ b1,  // [50]
    const float* __restrict__ W2,  // [50,2]
    const float* __restrict__ W3)  // [2,1]
{
    extern __shared__ char smem[];
    const uint32_t sb = smem_u32(smem);
    const int tid = threadIdx.x, wid = tid >> 5, lid = tid & 31;
    const int g = blockIdx.x;

    float* dinv_s = (float*)(smem + SM_DINV);
    float* q_s    = (float*)(smem + SM_Q);
    float* x_s    = (float*)(smem + SM_X);
    float* w1_s   = (float*)(smem + SM_W1);
    float* w_s    = (float*)(smem + SM_W);
    float* b1_s   = (float*)(smem + SM_B1);
    float* ep_s   = (float*)(smem + SM_EP);

    // --- Phase 0: zero A/ZH/ZL (pads must be 0), stage small tensors
    {
        uint4 z; z.x = z.y = z.z = z.w = 0u;
        // A..ZL contiguous: 138240 bytes = 8640 uint4
        for (int i = tid; i < 8640; i += 256)
            *reinterpret_cast<uint4*>(smem + SM_A + i * 16) = z;
    }
    {
        const float* xg = x + (size_t)g * 1000;
        for (int i = tid; i < 1000; i += 256) x_s[i] = xg[i];
        for (int i = tid; i < 250;  i += 256) w1_s[i] = W1[i];
        if (tid < 50) {
            w_s[tid]  = W2[tid * 2] * W3[0] + W2[tid * 2 + 1] * W3[1];
            b1_s[tid] = b1[tid];
        }
    }
    __syncthreads();

    // --- Phase 1: adjacency -> bf16 rows (stride 432B) + row degrees
    {
        const int4* ab = reinterpret_cast<const int4*>(adj) + (size_t)g * 10000;
        for (int row = wid; row < 200; row += 8) {
            const int4* arow = ab + row * 50;
            const uint32_t rbase = sb + SM_A + (uint32_t)row * STRA;
            int s = 0;
            for (int k = lid; k < 50; k += 32) {
                int4 v = arow[k];
                s += v.x + v.y + v.z + v.w;
                // int 0/1 -> packed bf16x2 (0x3F80 = bf16 1.0)
                uint32_t p0 = (uint32_t)v.x * 0x3F80u + (uint32_t)v.y * 0x3F800000u;
                uint32_t p1 = (uint32_t)v.z * 0x3F80u + (uint32_t)v.w * 0x3F800000u;
                asm volatile("st.shared.v2.u32 [%0], {%1, %2};"
                             :: "r"(rbase + (uint32_t)k * 8), "r"(p0), "r"(p1) : "memory");
            }
            #pragma unroll
            for (int o = 16; o > 0; o >>= 1) s += __shfl_down_sync(0xFFFFFFFFu, s, o);
            if (lid == 0) dinv_s[row] = (float)(s + 1);   // degree incl. self loop
        }
    }
    __syncthreads();

    // --- Phase 2: self loop on diagonal; deg -> dinv (0 for pad rows)
    if (tid < 200) {
        __nv_bfloat16* pp = (__nv_bfloat16*)(smem + SM_A + tid * STRA + tid * 2);
        *pp = __float2bfloat16(__bfloat162float(*pp) + 1.0f);
    }
    {
        float dv = (tid < 200) ? rsqrtf(dinv_s[tid]) : 0.0f;
        __syncthreads();                  // all deg reads done
        dinv_s[tid] = dv;
    }
    __syncthreads();

    // --- Phase 3: zd^T hi/lo bf16 into [f][m] rows (stride 432B)
    for (int idx = tid; idx < 5000; idx += 256) {
        int f  = idx / 100;
        int mp = idx - f * 100;
        int m0 = mp * 2;
        const float* xr = x_s + m0 * 5;
        float z0 = 0.f, z1 = 0.f;
        #pragma unroll
        for (int k = 0; k < 5; k++) {
            float wv = w1_s[k * 50 + f];
            z0 += xr[k] * wv;
            z1 += xr[5 + k] * wv;
        }
        z0 *= dinv_s[m0];
        z1 *= dinv_s[m0 + 1];
        __nv_bfloat16 h0 = __float2bfloat16(z0);
        __nv_bfloat16 h1 = __float2bfloat16(z1);
        __nv_bfloat16 l0 = __float2bfloat16(z0 - __bfloat162float(h0));
        __nv_bfloat16 l1 = __float2bfloat16(z1 - __bfloat162float(h1));
        uint32_t hp = (uint32_t)__bfloat16_as_ushort(h0) | ((uint32_t)__bfloat16_as_ushort(h1) << 16);
        uint32_t lp = (uint32_t)__bfloat16_as_ushort(l0) | ((uint32_t)__bfloat16_as_ushort(l1) << 16);
        uint32_t off = (uint32_t)f * STRA + (uint32_t)m0 * 2;
        *(uint32_t*)(smem + SM_ZH + off) = hp;
        *(uint32_t*)(smem + SM_ZL + off) = lp;
    }
    __syncthreads();

    // --- Phase 4: D = A @ zd via mma.sync. 13 M-tiles x 7 N-tiles.
    // Warp w owns mt = w and mt = w+8 (if < 13). Per k-step: load all 7 B hi+lo
    // fragments once, reuse across the warp's M-tiles.
    {
        // ldmatrix lane addressing
        const uint32_t a_lane = sb + SM_A + (uint32_t)(lid & 15) * STRA + (uint32_t)(lid >> 4) * 16;
        const uint32_t b_lane = (uint32_t)(lid & 7) * STRA + (uint32_t)((lid >> 3) & 1) * 16;
        const int mt1 = wid + 8;

        float acc[2][7][4];
        #pragma unroll
        for (int s = 0; s < 2; s++)
            #pragma unroll
            for (int nt = 0; nt < 7; nt++)
                #pragma unroll
                for (int i = 0; i < 4; i++) acc[s][nt][i] = 0.f;

        for (int k = 0; k < 13; ++k) {
            uint32_t bh[7][2], bl[7][2];
            #pragma unroll
            for (int nt = 0; nt < 7; ++nt) {
                uint32_t ba = sb + SM_ZH + (uint32_t)(nt * 8) * STRA + (uint32_t)k * 32 + b_lane;
                ldsm_x2(bh[nt][0], bh[nt][1], ba);
                ldsm_x2(bl[nt][0], bl[nt][1], ba + (SM_ZL - SM_ZH));
            }
            {
                uint32_t a0, a1, a2, a3;
                ldsm_x4(a0, a1, a2, a3, a_lane + (uint32_t)(wid * 16) * STRA + (uint32_t)k * 32);
                #pragma unroll
                for (int nt = 0; nt < 7; ++nt) {
                    mma16816(acc[0][nt], a0, a1, a2, a3, bh[nt][0], bh[nt][1]);
                    mma16816(acc[0][nt], a0, a1, a2, a3, bl[nt][0], bl[nt][1]);
                }
            }
            if (mt1 < 13) {
                uint32_t a0, a1, a2, a3;
                ldsm_x4(a0, a1, a2, a3, a_lane + (uint32_t)(mt1 * 16) * STRA + (uint32_t)k * 32);
                #pragma unroll
                for (int nt = 0; nt < 7; ++nt) {
                    mma16816(acc[1][nt], a0, a1, a2, a3, bh[nt][0], bh[nt][1]);
                    mma16816(acc[1][nt], a0, a1, a2, a3, bl[nt][0], bl[nt][1]);
                }
            }
        }

        // store C fragments to D. STRD = 228 B is 4-mod-8 -> odd rows are only
        // 4B-aligned, so stores MUST be scalar st.shared.f32 (v2 traps).
        #pragma unroll
        for (int s = 0; s < 2; ++s) {
            int mt = wid + s * 8;
            if (mt < 13) {
                #pragma unroll
                for (int nt = 0; nt < 7; ++nt) {
                    uint32_t r0 = (uint32_t)(mt * 16 + (lid >> 2));
                    uint32_t c4 = (uint32_t)(nt * 8 + (lid & 3) * 2) * 4;
                    uint32_t ad0 = sb + SM_D + r0 * STRD + c4;
                    asm volatile("st.shared.f32 [%0], %1;"
                                 :: "r"(ad0), "f"(acc[s][nt][0]) : "memory");
                    asm volatile("st.shared.f32 [%0], %1;"
                                 :: "r"(ad0 + 4u), "f"(acc[s][nt][1]) : "memory");
                    asm volatile("st.shared.f32 [%0], %1;"
                                 :: "r"(ad0 + 8u * STRD), "f"(acc[s][nt][2]) : "memory");
                    asm volatile("st.shared.f32 [%0], %1;"
                                 :: "r"(ad0 + 8u * STRD + 4u), "f"(acc[s][nt][3]) : "memory");
                }
            }
        }
    }
    __syncthreads();

    // --- Phase 5: per-atom silu + dot(w); q[n] = dinv[n]*p[n] (0 for pads)
    {
        int n = tid;
        float qv = 0.f;
        if (n < 200) {
            float dn = dinv_s[n];
            const float* Dr = (const float*)(smem + SM_D + n * STRD);
            float p = 0.f;
            #pragma unroll
            for (int f = 0; f < 50; ++f) {
                float h = dn * Dr[f] + b1_s[f];
                p += (h / (1.0f + __expf(-h))) * w_s[f];
            }
            qv = dn * p;
        }
        q_s[n] = qv;
    }
    __syncthreads();

    // --- Phase 6: e = sum_n dinv[n] * (A[n,:] . q)
    {
        float my = 0.f;
        for (int n = wid; n < 200; n += 8) {
            const char* Ar = smem + SM_A + n * STRA;
            float acc2 = 0.f;
            #pragma unroll
            for (int c = 0; c < 3; ++c) {       // m = 0..191
                uint32_t pr = *(const uint32_t*)(Ar + c * 128 + lid * 4);
                float2 a2 = __bfloat1622float2(*(const __nv_bfloat162*)&pr);
                float2 qq = *(const float2*)(smem + SM_Q + (c * 64 + lid * 2) * 4);
                acc2 += a2.x * qq.x + a2.y * qq.y;
            }
            if (lid < 8) {                       // m = 192..206 (A zero for m>=200)
                uint32_t pr = *(const uint32_t*)(Ar + 384 + lid * 4);
                float2 a2 = __bfloat1622float2(*(const __nv_bfloat162*)&pr);
                float2 qq = *(const float2*)(smem + SM_Q + (192 + lid * 2) * 4);
                acc2 += a2.x * qq.x + a2.y * qq.y;
            }
            #pragma unroll
            for (int o = 16; o > 0; o >>= 1) acc2 += __shfl_down_sync(0xFFFFFFFFu, acc2, o);
            if (lid == 0) my += dinv_s[n] * acc2;
        }
        if (lid == 0) ep_s[wid] = my;
    }
    __syncthreads();
    if (tid == 0) {
        float e = 0.f;
        #pragma unroll
        for (int i = 0; i < 8; i++) e += ep_s[i];
        g_e[g] = e;
    }
}

// ---------------------------------------------------------------------------
// Deterministic combine: out[b] = sum_r nu[b,r] * (e[r,b] + 200*(b2.W3 + b3))
// ---------------------------------------------------------------------------
__global__ void gnn_combine(const float* __restrict__ nu,  // [B,R]
                            const float* __restrict__ b2,  // [2]
                            const float* __restrict__ W3,  // [2]
                            const float* __restrict__ b3,  // [1]
                            float* __restrict__ out)       // [B]
{
    int b = threadIdx.x;
    float s3 = b2[0] * W3[0] + b2[1] * W3[1] + b3[0];
    float bias = 200.0f * s3;
    float acc = 0.f;
    #pragma unroll
    for (int r = 0; r < 4; r++)
        acc += nu[b * 4 + r] * (g_e[r * 256 + b] + bias);
    out[b] = acc;
}

// ---------------------------------------------------------------------------
extern "C" void kernel_launch(void* const* d_in, const int* in_sizes, int n_in,
                              void* d_out, int out_size) {
    const float* x   = (const float*)d_in[0];
    const int*   adj = (const int*)  d_in[1];
    const float* nu  = (const float*)d_in[2];
    const float* W1  = (const float*)d_in[3];
    const float* b1  = (const float*)d_in[4];
    const float* W2  = (const float*)d_in[5];
    const float* b2  = (const float*)d_in[6];
    const float* W3  = (const float*)d_in[7];
    const float* b3  = (const float*)d_in[8];

    cudaFuncSetAttribute(gnn_main, cudaFuncAttributeMaxDynamicSharedMemorySize, SM_TOTAL);

    gnn_main<<<1024, 256, SM_TOTAL>>>(x, adj, W1, b1, W2, W3);
    gnn_combine<<<1, 256>>>(nu, b2, W3, b3, (float*)d_out);
}

// round 5
// speedup vs baseline: 1.6305x; 1.6305x over previous
#include <cuda_runtime.h>
#include <cuda_bf16.h>
#include <cstdint>

// ---------------------------------------------------------------------------
// R=4, B=256, N=200, NF=5, H=50, OUT=2. grid g = r*256 + b. One CTA per graph.
//
// Per graph:
//   A       = adj + I (exact in bf16: {0,1,2})
//   deg[n]  = sum_m A[n,m];  dinv[n] = rsqrt(deg[n])
//   zd[m,f] = dinv[m] * (x @ W1)[m,f]
//   D[n,f]  = sum_m A[n,m] * zd[m,f]
//   q[m]    = dinv[m] * sum_f silu(dinv[m]*D[m,f] + b1[f]) * (W2@W3)[f]
//   e       = sum_n dinv[n] * (A[n,:] . q)
// out[b] = sum_r nu[b,r] * (e(r,b) + 200*(b2.W3 + b3))
//
// GEMM engine: warp-level mma.sync m16n8k16 bf16 (tcgen05 is sm_100a-only;
// this build targets plain sm_100).
// A operand [208x208] bf16 row-major, stride 432 B (conflict-free ldmatrix).
// B operand = zd^T [56 f][208 m] bf16 (= col-major B), hi + lo split
// accumulated into the same fp32 C fragments (A exact => order-free).
//
// R4 fix: adjacency loader front-batches 8 independent LDG.128 per thread
// (MLP 1-2 -> 8); degree computed from smem A afterwards (off the load path).
// ---------------------------------------------------------------------------

static constexpr int STRA = 432;                    // A row stride bytes (216 bf16)
static constexpr int STRD = 228;                    // D row stride bytes (57 f32)

static constexpr int SM_DINV = 0;                   // 256 f32
static constexpr int SM_Q    = 1024;                // 256 f32
static constexpr int SM_X    = 2048;                // 1000 f32
static constexpr int SM_W1   = 6048;                // 250 f32
static constexpr int SM_W    = 7048;                // 50 f32 (W2@W3)
static constexpr int SM_B1   = 7248;                // 50 f32
static constexpr int SM_EP   = 7456;                // 8 f32
static constexpr int SM_A    = 7552;                // 208*432 = 89856
static constexpr int SM_ZH   = SM_A  + 208 * STRA;  // 97408:  56*432 = 24192
static constexpr int SM_ZL   = SM_ZH + 56 * STRA;   // 121600: 56*432 = 24192
static constexpr int SM_D    = SM_ZL + 56 * STRA;   // 145792: 208*228 = 47424
static constexpr int SM_TOTAL= SM_D  + 208 * STRD;  // 193216 bytes

__device__ float g_e[1024];   // per-graph energy (deterministic combine kernel)

// ---------------------------------------------------------------------------
static __device__ __forceinline__ uint32_t smem_u32(const void* p) {
    uint32_t a;
    asm("{ .reg .u64 t; cvta.to.shared.u64 t, %1; cvt.u32.u64 %0, t; }" : "=r"(a) : "l"(p));
    return a;
}
static __device__ __forceinline__ void ldsm_x4(uint32_t& r0, uint32_t& r1,
                                               uint32_t& r2, uint32_t& r3, uint32_t a) {
    asm volatile("ldmatrix.sync.aligned.m8n8.x4.shared.b16 {%0,%1,%2,%3}, [%4];"
                 : "=r"(r0), "=r"(r1), "=r"(r2), "=r"(r3) : "r"(a));
}
static __device__ __forceinline__ void ldsm_x2(uint32_t& r0, uint32_t& r1, uint32_t a) {
    asm volatile("ldmatrix.sync.aligned.m8n8.x2.shared.b16 {%0,%1}, [%2];"
                 : "=r"(r0), "=r"(r1) : "r"(a));
}
static __device__ __forceinline__ void mma16816(float* c,
                                                uint32_t a0, uint32_t a1, uint32_t a2, uint32_t a3,
                                                uint32_t b0, uint32_t b1) {
    asm volatile("mma.sync.aligned.m16n8k16.row.col.f32.bf16.bf16.f32 "
                 "{%0,%1,%2,%3}, {%4,%5,%6,%7}, {%8,%9}, {%0,%1,%2,%3};"
                 : "+f"(c[0]), "+f"(c[1]), "+f"(c[2]), "+f"(c[3])
                 : "r"(a0), "r"(a1), "r"(a2), "r"(a3), "r"(b0), "r"(b1));
}

// ---------------------------------------------------------------------------
__global__ void __launch_bounds__(256, 1) gnn_main(
    const float* __restrict__ x,   // [R,B,200,5]
    const int*   __restrict__ adj, // [R,B,200,200]
    const float* __restrict__ W1,  // [5,50]
    const float* __restrict__ b1,  // [50]
    const float* __restrict__ W2,  // [50,2]
    const float* __restrict__ W3)  // [2,1]
{
    extern __shared__ char smem[];
    const uint32_t sb = smem_u32(smem);
    const int tid = threadIdx.x, wid = tid >> 5, lid = tid & 31;
    const int g = blockIdx.x;

    float* dinv_s = (float*)(smem + SM_DINV);
    float* q_s    = (float*)(smem + SM_Q);
    float* x_s    = (float*)(smem + SM_X);
    float* w1_s   = (float*)(smem + SM_W1);
    float* w_s    = (float*)(smem + SM_W);
    float* b1_s   = (float*)(smem + SM_B1);
    float* ep_s   = (float*)(smem + SM_EP);

    // --- Phase 0: zero A/ZH/ZL (pads must be 0), stage small tensors
    {
        uint4 z; z.x = z.y = z.z = z.w = 0u;
        // A..ZL contiguous: 138240 bytes = 8640 uint4
        for (int i = tid; i < 8640; i += 256)
            *reinterpret_cast<uint4*>(smem + SM_A + i * 16) = z;
    }
    {
        const float* xg = x + (size_t)g * 1000;
        for (int i = tid; i < 1000; i += 256) x_s[i] = xg[i];
        for (int i = tid; i < 250;  i += 256) w1_s[i] = W1[i];
        if (tid < 50) {
            w_s[tid]  = W2[tid * 2] * W3[0] + W2[tid * 2 + 1] * W3[1];
            b1_s[tid] = b1[tid];
        }
    }
    __syncthreads();

    // --- Phase 1: adjacency -> bf16 rows (stride 432B), front-batched loads.
    // Flat view: 10000 int4 (each = 4 adjacency ints = 4 bf16 = 8 smem bytes).
    // 5 batches of 8 independent LDG.128 per thread (last batch predicated).
    {
        const int4* ab = reinterpret_cast<const int4*>(adj) + (size_t)g * 10000;
        #pragma unroll 1
        for (int base = 0; base < 10000; base += 2048) {
            int4 v[8];
            #pragma unroll
            for (int i = 0; i < 8; ++i) {
                int idx = base + i * 256 + tid;
                if (idx < 10000) v[i] = ab[idx];
                else             v[i] = make_int4(0, 0, 0, 0);
            }
            #pragma unroll
            for (int i = 0; i < 8; ++i) {
                int idx = base + i * 256 + tid;
                if (idx < 10000) {
                    int row = idx / 50;
                    int c   = idx - row * 50;
                    // int 0/1 -> packed bf16x2 (0x3F80 = bf16 1.0)
                    uint2 p;
                    p.x = (uint32_t)v[i].x * 0x3F80u + (uint32_t)v[i].y * 0x3F800000u;
                    p.y = (uint32_t)v[i].z * 0x3F80u + (uint32_t)v[i].w * 0x3F800000u;
                    *reinterpret_cast<uint2*>(smem + SM_A + row * STRA + c * 8) = p;
                }
            }
        }
    }
    __syncthreads();

    // --- Phase 2a: self loop on diagonal (A[n,n] += 1; exact {1,2})
    if (tid < 200) {
        __nv_bfloat16* pp = (__nv_bfloat16*)(smem + SM_A + tid * STRA + tid * 2);
        *pp = __float2bfloat16(__bfloat162float(*pp) + 1.0f);
    }
    __syncthreads();

    // --- Phase 2b: deg[n] = rowsum of A (incl. self loop); dinv = rsqrt(deg)
    {
        for (int row = wid; row < 200; row += 8) {
            const uint32_t* Ar = (const uint32_t*)(smem + SM_A + row * STRA);
            float s = 0.f;
            #pragma unroll
            for (int c = 0; c < 3; ++c) {       // words 0..95  (m = 0..191)
                uint32_t pr = Ar[c * 32 + lid];
                float2 a2 = __bfloat1622float2(*(const __nv_bfloat162*)&pr);
                s += a2.x + a2.y;
            }
            if (lid < 4) {                       // words 96..99 (m = 192..199)
                uint32_t pr = Ar[96 + lid];
                float2 a2 = __bfloat1622float2(*(const __nv_bfloat162*)&pr);
                s += a2.x + a2.y;
            }
            #pragma unroll
            for (int o = 16; o > 0; o >>= 1) s += __shfl_down_sync(0xFFFFFFFFu, s, o);
            if (lid == 0) dinv_s[row] = rsqrtf(s);
        }
    }
    __syncthreads();

    // --- Phase 3: zd^T hi/lo bf16 into [f][m] rows (stride 432B)
    for (int idx = tid; idx < 5000; idx += 256) {
        int f  = idx / 100;
        int mp = idx - f * 100;
        int m0 = mp * 2;
        const float* xr = x_s + m0 * 5;
        float z0 = 0.f, z1 = 0.f;
        #pragma unroll
        for (int k = 0; k < 5; k++) {
            float wv = w1_s[k * 50 + f];
            z0 += xr[k] * wv;
            z1 += xr[5 + k] * wv;
        }
        z0 *= dinv_s[m0];
        z1 *= dinv_s[m0 + 1];
        __nv_bfloat16 h0 = __float2bfloat16(z0);
        __nv_bfloat16 h1 = __float2bfloat16(z1);
        __nv_bfloat16 l0 = __float2bfloat16(z0 - __bfloat162float(h0));
        __nv_bfloat16 l1 = __float2bfloat16(z1 - __bfloat162float(h1));
        uint32_t hp = (uint32_t)__bfloat16_as_ushort(h0) | ((uint32_t)__bfloat16_as_ushort(h1) << 16);
        uint32_t lp = (uint32_t)__bfloat16_as_ushort(l0) | ((uint32_t)__bfloat16_as_ushort(l1) << 16);
        uint32_t off = (uint32_t)f * STRA + (uint32_t)m0 * 2;
        *(uint32_t*)(smem + SM_ZH + off) = hp;
        *(uint32_t*)(smem + SM_ZL + off) = lp;
    }
    __syncthreads();

    // --- Phase 4: D = A @ zd via mma.sync. 13 M-tiles x 7 N-tiles.
    // Warp w owns mt = w and mt = w+8 (if < 13). Per k-step: load all 7 B hi+lo
    // fragments once, reuse across the warp's M-tiles.
    {
        const uint32_t a_lane = sb + SM_A + (uint32_t)(lid & 15) * STRA + (uint32_t)(lid >> 4) * 16;
        const uint32_t b_lane = (uint32_t)(lid & 7) * STRA + (uint32_t)((lid >> 3) & 1) * 16;
        const int mt1 = wid + 8;

        float acc[2][7][4];
        #pragma unroll
        for (int s = 0; s < 2; s++)
            #pragma unroll
            for (int nt = 0; nt < 7; nt++)
                #pragma unroll
                for (int i = 0; i < 4; i++) acc[s][nt][i] = 0.f;

        for (int k = 0; k < 13; ++k) {
            uint32_t bh[7][2], bl[7][2];
            #pragma unroll
            for (int nt = 0; nt < 7; ++nt) {
                uint32_t ba = sb + SM_ZH + (uint32_t)(nt * 8) * STRA + (uint32_t)k * 32 + b_lane;
                ldsm_x2(bh[nt][0], bh[nt][1], ba);
                ldsm_x2(bl[nt][0], bl[nt][1], ba + (SM_ZL - SM_ZH));
            }
            {
                uint32_t a0, a1, a2, a3;
                ldsm_x4(a0, a1, a2, a3, a_lane + (uint32_t)(wid * 16) * STRA + (uint32_t)k * 32);
                #pragma unroll
                for (int nt = 0; nt < 7; ++nt) {
                    mma16816(acc[0][nt], a0, a1, a2, a3, bh[nt][0], bh[nt][1]);
                    mma16816(acc[0][nt], a0, a1, a2, a3, bl[nt][0], bl[nt][1]);
                }
            }
            if (mt1 < 13) {
                uint32_t a0, a1, a2, a3;
                ldsm_x4(a0, a1, a2, a3, a_lane + (uint32_t)(mt1 * 16) * STRA + (uint32_t)k * 32);
                #pragma unroll
                for (int nt = 0; nt < 7; ++nt) {
                    mma16816(acc[1][nt], a0, a1, a2, a3, bh[nt][0], bh[nt][1]);
                    mma16816(acc[1][nt], a0, a1, a2, a3, bl[nt][0], bl[nt][1]);
                }
            }
        }

        // store C fragments to D. STRD = 228 B is 4-mod-8 -> odd rows are only
        // 4B-aligned, so stores MUST be scalar st.shared.f32 (v2 traps).
        #pragma unroll
        for (int s = 0; s < 2; ++s) {
            int mt = wid + s * 8;
            if (mt < 13) {
                #pragma unroll
                for (int nt = 0; nt < 7; ++nt) {
                    uint32_t r0 = (uint32_t)(mt * 16 + (lid >> 2));
                    uint32_t c4 = (uint32_t)(nt * 8 + (lid & 3) * 2) * 4;
                    uint32_t ad0 = sb + SM_D + r0 * STRD + c4;
                    asm volatile("st.shared.f32 [%0], %1;"
                                 :: "r"(ad0), "f"(acc[s][nt][0]) : "memory");
                    asm volatile("st.shared.f32 [%0], %1;"
                                 :: "r"(ad0 + 4u), "f"(acc[s][nt][1]) : "memory");
                    asm volatile("st.shared.f32 [%0], %1;"
                                 :: "r"(ad0 + 8u * STRD), "f"(acc[s][nt][2]) : "memory");
                    asm volatile("st.shared.f32 [%0], %1;"
                                 :: "r"(ad0 + 8u * STRD + 4u), "f"(acc[s][nt][3]) : "memory");
                }
            }
        }
    }
    __syncthreads();

    // --- Phase 5: per-atom silu + dot(w); q[n] = dinv[n]*p[n] (0 for pads)
    {
        int n = tid;
        float qv = 0.f;
        if (n < 200) {
            float dn = dinv_s[n];
            const float* Dr = (const float*)(smem + SM_D + n * STRD);
            float p = 0.f;
            #pragma unroll
            for (int f = 0; f < 50; ++f) {
                float h = dn * Dr[f] + b1_s[f];
                p += (h / (1.0f + __expf(-h))) * w_s[f];
            }
            qv = dn * p;
        }
        q_s[n] = qv;
    }
    __syncthreads();

    // --- Phase 6: e = sum_n dinv[n] * (A[n,:] . q)
    {
        float my = 0.f;
        for (int n = wid; n < 200; n += 8) {
            const char* Ar = smem + SM_A + n * STRA;
            float acc2 = 0.f;
            #pragma unroll
            for (int c = 0; c < 3; ++c) {       // m = 0..191
                uint32_t pr = *(const uint32_t*)(Ar + c * 128 + lid * 4);
                float2 a2 = __bfloat1622float2(*(const __nv_bfloat162*)&pr);
                float2 qq = *(const float2*)(smem + SM_Q + (c * 64 + lid * 2) * 4);
                acc2 += a2.x * qq.x + a2.y * qq.y;
            }
            if (lid < 8) {                       // m = 192..207 (A zero for m>=200)
                uint32_t pr = *(const uint32_t*)(Ar + 384 + lid * 4);
                float2 a2 = __bfloat1622float2(*(const __nv_bfloat162*)&pr);
                float2 qq = *(const float2*)(smem + SM_Q + (192 + lid * 2) * 4);
                acc2 += a2.x * qq.x + a2.y * qq.y;
            }
            #pragma unroll
            for (int o = 16; o > 0; o >>= 1) acc2 += __shfl_down_sync(0xFFFFFFFFu, acc2, o);
            if (lid == 0) my += dinv_s[n] * acc2;
        }
        if (lid == 0) ep_s[wid] = my;
    }
    __syncthreads();
    if (tid == 0) {
        float e = 0.f;
        #pragma unroll
        for (int i = 0; i < 8; i++) e += ep_s[i];
        g_e[g] = e;
    }
}

// ---------------------------------------------------------------------------
// Deterministic combine: out[b] = sum_r nu[b,r] * (e[r,b] + 200*(b2.W3 + b3))
// ---------------------------------------------------------------------------
__global__ void gnn_combine(const float* __restrict__ nu,  // [B,R]
                            const float* __restrict__ b2,  // [2]
                            const float* __restrict__ W3,  // [2]
                            const float* __restrict__ b3,  // [1]
                            float* __restrict__ out)       // [B]
{
    int b = threadIdx.x;
    float s3 = b2[0] * W3[0] + b2[1] * W3[1] + b3[0];
    float bias = 200.0f * s3;
    float acc = 0.f;
    #pragma unroll
    for (int r = 0; r < 4; r++)
        acc += nu[b * 4 + r] * (g_e[r * 256 + b] + bias);
    out[b] = acc;
}

// ---------------------------------------------------------------------------
extern "C" void kernel_launch(void* const* d_in, const int* in_sizes, int n_in,
                              void* d_out, int out_size) {
    const float* x   = (const float*)d_in[0];
    const int*   adj = (const int*)  d_in[1];
    const float* nu  = (const float*)d_in[2];
    const float* W1  = (const float*)d_in[3];
    const float* b1  = (const float*)d_in[4];
    const float* W2  = (const float*)d_in[5];
    const float* b2  = (const float*)d_in[6];
    const float* W3  = (const float*)d_in[7];
    const float* b3  = (const float*)d_in[8];

    cudaFuncSetAttribute(gnn_main, cudaFuncAttributeMaxDynamicSharedMemorySize, SM_TOTAL);

    gnn_main<<<1024, 256, SM_TOTAL>>>(x, adj, W1, b1, W2, W3);
    gnn_combine<<<1, 256>>>(nu, b2, W3, b3, (float*)d_out);
}

// round 6
// speedup vs baseline: 1.6439x; 1.0082x over previous
#include <cuda_runtime.h>
#include <cuda_bf16.h>
#include <cstdint>

// ---------------------------------------------------------------------------
// R=4, B=256, N=200, NF=5, H=50, OUT=2. grid g = r*256 + b. One CTA per graph.
//
// Per graph:
//   A       = adj + I (exact in bf16: {0,1,2})
//   deg[n]  = sum_m A[n,m];  dinv[n] = rsqrt(deg[n])
//   zd[m,f] = dinv[m] * (x @ W1)[m,f]
//   D[n,f]  = sum_m A[n,m] * zd[m,f]
//   q[m]    = dinv[m] * sum_f silu(dinv[m]*D[m,f] + b1[f]) * (W2@W3)[f]
//   e       = sum_n dinv[n] * (A[n,:] . q)
// out[b] = sum_r nu[b,r] * (e(r,b) + 200*(b2.W3 + b3))
//
// GEMM engine: warp-level mma.sync m16n8k16 bf16 (tcgen05 is sm_100a-only;
// this build targets plain sm_100).
// A operand [208x208] bf16 row-major, stride 432 B (conflict-free ldmatrix).
// B operand = zd^T [56 f][208 m] bf16 (= col-major B), hi + lo split
// accumulated into the same fp32 C fragments (A exact => order-free).
//
// R6: combine fused into gnn_main via last-block pattern (kills 2nd launch,
// makes ncu -s5 land on the hot kernel); targeted pad zeroing (13KB vs 138KB);
// loader MLP 10.
// ---------------------------------------------------------------------------

static constexpr int STRA = 432;                    // A row stride bytes (216 bf16)
static constexpr int STRD = 228;                    // D row stride bytes (57 f32)

static constexpr int SM_DINV = 0;                   // 256 f32
static constexpr int SM_Q    = 1024;                // 256 f32
static constexpr int SM_X    = 2048;                // 1000 f32
static constexpr int SM_W1   = 6048;                // 250 f32
static constexpr int SM_W    = 7048;                // 50 f32 (W2@W3)
static constexpr int SM_B1   = 7248;                // 50 f32
static constexpr int SM_EP   = 7456;                // 8 f32
static constexpr int SM_FLAG = 7488;                // 1 int (last-block flag)
static constexpr int SM_A    = 7552;                // 208*432 = 89856
static constexpr int SM_ZH   = SM_A  + 208 * STRA;  // 97408:  56*432 = 24192
static constexpr int SM_ZL   = SM_ZH + 56 * STRA;   // 121600: 56*432 = 24192
static constexpr int SM_D    = SM_ZL + 56 * STRA;   // 145792: 208*228 = 47424
static constexpr int SM_TOTAL= SM_D  + 208 * STRD;  // 193216 bytes

__device__ float g_e[1024];          // per-graph energy
__device__ unsigned int g_ctr = 0;   // last-block counter (reset each launch)

// ---------------------------------------------------------------------------
static __device__ __forceinline__ uint32_t smem_u32(const void* p) {
    uint32_t a;
    asm("{ .reg .u64 t; cvta.to.shared.u64 t, %1; cvt.u32.u64 %0, t; }" : "=r"(a) : "l"(p));
    return a;
}
static __device__ __forceinline__ void ldsm_x4(uint32_t& r0, uint32_t& r1,
                                               uint32_t& r2, uint32_t& r3, uint32_t a) {
    asm volatile("ldmatrix.sync.aligned.m8n8.x4.shared.b16 {%0,%1,%2,%3}, [%4];"
                 : "=r"(r0), "=r"(r1), "=r"(r2), "=r"(r3) : "r"(a));
}
static __device__ __forceinline__ void ldsm_x2(uint32_t& r0, uint32_t& r1, uint32_t a) {
    asm volatile("ldmatrix.sync.aligned.m8n8.x2.shared.b16 {%0,%1}, [%2];"
                 : "=r"(r0), "=r"(r1) : "r"(a));
}
static __device__ __forceinline__ void mma16816(float* c,
                                                uint32_t a0, uint32_t a1, uint32_t a2, uint32_t a3,
                                                uint32_t b0, uint32_t b1) {
    asm volatile("mma.sync.aligned.m16n8k16.row.col.f32.bf16.bf16.f32 "
                 "{%0,%1,%2,%3}, {%4,%5,%6,%7}, {%8,%9}, {%0,%1,%2,%3};"
                 : "+f"(c[0]), "+f"(c[1]), "+f"(c[2]), "+f"(c[3])
                 : "r"(a0), "r"(a1), "r"(a2), "r"(a3), "r"(b0), "r"(b1));
}

// ---------------------------------------------------------------------------
__global__ void __launch_bounds__(256, 1) gnn_main(
    const float* __restrict__ x,   // [R,B,200,5]
    const int*   __restrict__ adj, // [R,B,200,200]
    const float* __restrict__ nu,  // [B,R]
    const float* __restrict__ W1,  // [5,50]
    const float* __restrict__ b1,  // [50]
    const float* __restrict__ W2,  // [50,2]
    const float* __restrict__ b2,  // [2]
    const float* __restrict__ W3,  // [2,1]
    const float* __restrict__ b3,  // [1]
    float* __restrict__ out)       // [B]
{
    extern __shared__ char smem[];
    const uint32_t sb = smem_u32(smem);
    const int tid = threadIdx.x, wid = tid >> 5, lid = tid & 31;
    const int g = blockIdx.x;

    float* dinv_s = (float*)(smem + SM_DINV);
    float* q_s    = (float*)(smem + SM_Q);
    float* x_s    = (float*)(smem + SM_X);
    float* w1_s   = (float*)(smem + SM_W1);
    float* w_s    = (float*)(smem + SM_W);
    float* b1_s   = (float*)(smem + SM_B1);
    float* ep_s   = (float*)(smem + SM_EP);

    // --- Phase 0: targeted pad zeroing (only regions ldsm/epilogue ever read)
    {
        uint4 z; z.x = z.y = z.z = z.w = 0u;
        // A rows 0..199, cols 200..207 (16B @ row*432+400)
        if (tid < 200) *reinterpret_cast<uint4*>(smem + SM_A + tid * STRA + 400) = z;
        // ZH/ZL rows f=0..49, m=200..207
        if (tid < 50) {
            *reinterpret_cast<uint4*>(smem + SM_ZH + tid * STRA + 400) = z;
            *reinterpret_cast<uint4*>(smem + SM_ZL + tid * STRA + 400) = z;
        }
        // A rows 200..207, cols 0..207 (26 uint4/row * 8 rows)
        for (int i = tid; i < 208; i += 256) {
            int r = i / 26, c = i - r * 26;
            *reinterpret_cast<uint4*>(smem + SM_A + (200 + r) * STRA + c * 16) = z;
        }
        // ZH/ZL rows f=50..55, m=0..207 (26 uint4/row * 6 rows)
        for (int i = tid; i < 156; i += 256) {
            int r = i / 26, c = i - r * 26;
            *reinterpret_cast<uint4*>(smem + SM_ZH + (50 + r) * STRA + c * 16) = z;
            *reinterpret_cast<uint4*>(smem + SM_ZL + (50 + r) * STRA + c * 16) = z;
        }
    }
    {
        const float* xg = x + (size_t)g * 1000;
        for (int i = tid; i < 1000; i += 256) x_s[i] = xg[i];
        for (int i = tid; i < 250;  i += 256) w1_s[i] = W1[i];
        if (tid < 50) {
            w_s[tid]  = W2[tid * 2] * W3[0] + W2[tid * 2 + 1] * W3[1];
            b1_s[tid] = b1[tid];
        }
    }
    // No sync needed yet: Phase 1 writes disjoint smem (A cols 0..199 of rows
    // 0..199); sync before first read below.

    // --- Phase 1: adjacency -> bf16 rows, front-batched (MLP=10 per thread).
    // Flat: 10000 int4 (4 ints = 4 bf16 = 8 smem bytes). 4 batches of 10x256.
    {
        const int4* ab = reinterpret_cast<const int4*>(adj) + (size_t)g * 10000;
        #pragma unroll 1
        for (int base = 0; base < 10000; base += 2560) {
            int4 v[10];
            #pragma unroll
            for (int i = 0; i < 10; ++i) {
                int idx = base + i * 256 + tid;
                if (idx < 10000) v[i] = ab[idx];
                else             v[i] = make_int4(0, 0, 0, 0);
            }
            #pragma unroll
            for (int i = 0; i < 10; ++i) {
                int idx = base + i * 256 + tid;
                if (idx < 10000) {
                    int row = idx / 50;
                    int c   = idx - row * 50;
                    uint2 p;   // int 0/1 -> packed bf16x2 (0x3F80 = bf16 1.0)
                    p.x = (uint32_t)v[i].x * 0x3F80u + (uint32_t)v[i].y * 0x3F800000u;
                    p.y = (uint32_t)v[i].z * 0x3F80u + (uint32_t)v[i].w * 0x3F800000u;
                    *reinterpret_cast<uint2*>(smem + SM_A + row * STRA + c * 8) = p;
                }
            }
        }
    }
    __syncthreads();

    // --- Phase 2a: self loop on diagonal (A[n,n] += 1; exact {1,2})
    if (tid < 200) {
        __nv_bfloat16* pp = (__nv_bfloat16*)(smem + SM_A + tid * STRA + tid * 2);
        *pp = __float2bfloat16(__bfloat162float(*pp) + 1.0f);
    }
    __syncthreads();

    // --- Phase 2b: deg[n] = rowsum of A (incl. self loop); dinv = rsqrt(deg)
    {
        for (int row = wid; row < 200; row += 8) {
            const uint32_t* Ar = (const uint32_t*)(smem + SM_A + row * STRA);
            float s = 0.f;
            #pragma unroll
            for (int c = 0; c < 3; ++c) {
                uint32_t pr = Ar[c * 32 + lid];
                float2 a2 = __bfloat1622float2(*(const __nv_bfloat162*)&pr);
                s += a2.x + a2.y;
            }
            if (lid < 4) {
                uint32_t pr = Ar[96 + lid];
                float2 a2 = __bfloat1622float2(*(const __nv_bfloat162*)&pr);
                s += a2.x + a2.y;
            }
            #pragma unroll
            for (int o = 16; o > 0; o >>= 1) s += __shfl_down_sync(0xFFFFFFFFu, s, o);
            if (lid == 0) dinv_s[row] = rsqrtf(s);
        }
    }
    __syncthreads();

    // --- Phase 3: zd^T hi/lo bf16 into [f][m] rows (stride 432B)
    for (int idx = tid; idx < 5000; idx += 256) {
        int f  = idx / 100;
        int mp = idx - f * 100;
        int m0 = mp * 2;
        const float* xr = x_s + m0 * 5;
        float z0 = 0.f, z1 = 0.f;
        #pragma unroll
        for (int k = 0; k < 5; k++) {
            float wv = w1_s[k * 50 + f];
            z0 += xr[k] * wv;
            z1 += xr[5 + k] * wv;
        }
        z0 *= dinv_s[m0];
        z1 *= dinv_s[m0 + 1];
        __nv_bfloat16 h0 = __float2bfloat16(z0);
        __nv_bfloat16 h1 = __float2bfloat16(z1);
        __nv_bfloat16 l0 = __float2bfloat16(z0 - __bfloat162float(h0));
        __nv_bfloat16 l1 = __float2bfloat16(z1 - __bfloat162float(h1));
        uint32_t hp = (uint32_t)__bfloat16_as_ushort(h0) | ((uint32_t)__bfloat16_as_ushort(h1) << 16);
        uint32_t lp = (uint32_t)__bfloat16_as_ushort(l0) | ((uint32_t)__bfloat16_as_ushort(l1) << 16);
        uint32_t off = (uint32_t)f * STRA + (uint32_t)m0 * 2;
        *(uint32_t*)(smem + SM_ZH + off) = hp;
        *(uint32_t*)(smem + SM_ZL + off) = lp;
    }
    __syncthreads();

    // --- Phase 4: D = A @ zd via mma.sync. 13 M-tiles x 7 N-tiles.
    {
        const uint32_t a_lane = sb + SM_A + (uint32_t)(lid & 15) * STRA + (uint32_t)(lid >> 4) * 16;
        const uint32_t b_lane = (uint32_t)(lid & 7) * STRA + (uint32_t)((lid >> 3) & 1) * 16;
        const int mt1 = wid + 8;

        float acc[2][7][4];
        #pragma unroll
        for (int s = 0; s < 2; s++)
            #pragma unroll
            for (int nt = 0; nt < 7; nt++)
                #pragma unroll
                for (int i = 0; i < 4; i++) acc[s][nt][i] = 0.f;

        for (int k = 0; k < 13; ++k) {
            uint32_t bh[7][2], bl[7][2];
            #pragma unroll
            for (int nt = 0; nt < 7; ++nt) {
                uint32_t ba = sb + SM_ZH + (uint32_t)(nt * 8) * STRA + (uint32_t)k * 32 + b_lane;
                ldsm_x2(bh[nt][0], bh[nt][1], ba);
                ldsm_x2(bl[nt][0], bl[nt][1], ba + (SM_ZL - SM_ZH));
            }
            {
                uint32_t a0, a1, a2, a3;
                ldsm_x4(a0, a1, a2, a3, a_lane + (uint32_t)(wid * 16) * STRA + (uint32_t)k * 32);
                #pragma unroll
                for (int nt = 0; nt < 7; ++nt) {
                    mma16816(acc[0][nt], a0, a1, a2, a3, bh[nt][0], bh[nt][1]);
                    mma16816(acc[0][nt], a0, a1, a2, a3, bl[nt][0], bl[nt][1]);
                }
            }
            if (mt1 < 13) {
                uint32_t a0, a1, a2, a3;
                ldsm_x4(a0, a1, a2, a3, a_lane + (uint32_t)(mt1 * 16) * STRA + (uint32_t)k * 32);
                #pragma unroll
                for (int nt = 0; nt < 7; ++nt) {
                    mma16816(acc[1][nt], a0, a1, a2, a3, bh[nt][0], bh[nt][1]);
                    mma16816(acc[1][nt], a0, a1, a2, a3, bl[nt][0], bl[nt][1]);
                }
            }
        }

        // store C fragments to D. STRD = 228 B is 4-mod-8 -> scalar stores only.
        #pragma unroll
        for (int s = 0; s < 2; ++s) {
            int mt = wid + s * 8;
            if (mt < 13) {
                #pragma unroll
                for (int nt = 0; nt < 7; ++nt) {
                    uint32_t r0 = (uint32_t)(mt * 16 + (lid >> 2));
                    uint32_t c4 = (uint32_t)(nt * 8 + (lid & 3) * 2) * 4;
                    uint32_t ad0 = sb + SM_D + r0 * STRD + c4;
                    asm volatile("st.shared.f32 [%0], %1;"
                                 :: "r"(ad0), "f"(acc[s][nt][0]) : "memory");
                    asm volatile("st.shared.f32 [%0], %1;"
                                 :: "r"(ad0 + 4u), "f"(acc[s][nt][1]) : "memory");
                    asm volatile("st.shared.f32 [%0], %1;"
                                 :: "r"(ad0 + 8u * STRD), "f"(acc[s][nt][2]) : "memory");
                    asm volatile("st.shared.f32 [%0], %1;"
                                 :: "r"(ad0 + 8u * STRD + 4u), "f"(acc[s][nt][3]) : "memory");
                }
            }
        }
    }
    __syncthreads();

    // --- Phase 5: per-atom silu + dot(w); q[n] = dinv[n]*p[n] (0 for pads)
    {
        int n = tid;
        float qv = 0.f;
        if (n < 200) {
            float dn = dinv_s[n];
            const float* Dr = (const float*)(smem + SM_D + n * STRD);
            float p = 0.f;
            #pragma unroll
            for (int f = 0; f < 50; ++f) {
                float h = dn * Dr[f] + b1_s[f];
                p += (h / (1.0f + __expf(-h))) * w_s[f];
            }
            qv = dn * p;
        }
        q_s[n] = qv;
    }
    __syncthreads();

    // --- Phase 6: e = sum_n dinv[n] * (A[n,:] . q)
    {
        float my = 0.f;
        for (int n = wid; n < 200; n += 8) {
            const char* Ar = smem + SM_A + n * STRA;
            float acc2 = 0.f;
            #pragma unroll
            for (int c = 0; c < 3; ++c) {       // m = 0..191
                uint32_t pr = *(const uint32_t*)(Ar + c * 128 + lid * 4);
                float2 a2 = __bfloat1622float2(*(const __nv_bfloat162*)&pr);
                float2 qq = *(const float2*)(smem + SM_Q + (c * 64 + lid * 2) * 4);
                acc2 += a2.x * qq.x + a2.y * qq.y;
            }
            if (lid < 8) {                       // m = 192..207 (pads zero)
                uint32_t pr = *(const uint32_t*)(Ar + 384 + lid * 4);
                float2 a2 = __bfloat1622float2(*(const __nv_bfloat162*)&pr);
                float2 qq = *(const float2*)(smem + SM_Q + (192 + lid * 2) * 4);
                acc2 += a2.x * qq.x + a2.y * qq.y;
            }
            #pragma unroll
            for (int o = 16; o > 0; o >>= 1) acc2 += __shfl_down_sync(0xFFFFFFFFu, acc2, o);
            if (lid == 0) my += dinv_s[n] * acc2;
        }
        if (lid == 0) ep_s[wid] = my;
    }
    __syncthreads();

    // --- Tail: publish e; last block does the deterministic combine.
    if (tid == 0) {
        float e = 0.f;
        #pragma unroll
        for (int i = 0; i < 8; i++) e += ep_s[i];
        g_e[g] = e;
        __threadfence();
        unsigned v = atomicAdd(&g_ctr, 1u);
        *(int*)(smem + SM_FLAG) = (v == (unsigned)(gridDim.x - 1)) ? 1 : 0;
    }
    __syncthreads();
    if (*(int*)(smem + SM_FLAG)) {
        if (tid == 0) g_ctr = 0;                 // reset for next graph replay
        volatile const float* ge = g_e;          // bypass L1: peers' writes are L2-visible
        float s3 = b2[0] * W3[0] + b2[1] * W3[1] + b3[0];
        float bias = 200.0f * s3;
        int b = tid;                              // 256 threads = 256 outputs
        float acc = 0.f;
        #pragma unroll
        for (int r = 0; r < 4; r++)
            acc += nu[b * 4 + r] * (ge[r * 256 + b] + bias);
        out[b] = acc;
    }
}

// ---------------------------------------------------------------------------
extern "C" void kernel_launch(void* const* d_in, const int* in_sizes, int n_in,
                              void* d_out, int out_size) {
    const float* x   = (const float*)d_in[0];
    const int*   adj = (const int*)  d_in[1];
    const float* nu  = (const float*)d_in[2];
    const float* W1  = (const float*)d_in[3];
    const float* b1  = (const float*)d_in[4];
    const float* W2  = (const float*)d_in[5];
    const float* b2  = (const float*)d_in[6];
    const float* W3  = (const float*)d_in[7];
    const float* b3  = (const float*)d_in[8];

    cudaFuncSetAttribute(gnn_main, cudaFuncAttributeMaxDynamicSharedMemorySize, SM_TOTAL);

    gnn_main<<<1024, 256, SM_TOTAL>>>(x, adj, nu, W1, b1, W2, b2, W3, b3,
                                      (float*)d_out);
}

// round 7
// speedup vs baseline: 2.0946x; 1.2742x over previous
#include <cuda_runtime.h>
#include <cuda_bf16.h>
#include <cstdint>

// ---------------------------------------------------------------------------
// R=4, B=256, N=200, NF=5, H=50, OUT=2. grid g = r*256 + b. One CTA per graph.
//
// Per graph:
//   A       = adj + I (exact in bf16: {0,1,2})
//   deg[n]  = sum_m A[n,m];  dinv[n] = rsqrt(deg[n])
//   zd[m,f] = dinv[m] * (x @ W1)[m,f]
//   D[n,f]  = sum_m A[n,m] * zd[m,f]
//   q[m]    = dinv[m] * sum_f silu(dinv[m]*D[m,f] + b1[f]) * (W2@W3)[f]
//   e       = sum_n dinv[n] * (A[n,:] . q)
// out[b] = sum_r nu[b,r] * (e(r,b) + 200*(b2.W3 + b3))
//
// GEMM engine: warp-level mma.sync m16n8k16 bf16 (tcgen05 is sm_100a-only).
// A operand [208x208] bf16 row-major, stride 432 B (conflict-free ldmatrix).
// B operand = zd^T [56 f][208 m] bf16 (= col-major B), hi + lo split
// accumulated into the same fp32 C fragments (A exact => order-free).
//
// R7: 512 threads/CTA (16 warps) — profile showed occ 12.5% / issue 24% with
// nothing saturated => latency-bound on warp count. One M-tile per warp,
// loader = 2 batches of MLP-10, row phases strided by 16.
// ---------------------------------------------------------------------------

static constexpr int THREADS = 512;

static constexpr int STRA = 432;                    // A row stride bytes (216 bf16)
static constexpr int STRD = 228;                    // D row stride bytes (57 f32)

static constexpr int SM_DINV = 0;                   // 256 f32
static constexpr int SM_Q    = 1024;                // 256 f32
static constexpr int SM_X    = 2048;                // 1000 f32
static constexpr int SM_W1   = 6048;                // 250 f32
static constexpr int SM_W    = 7048;                // 50 f32 (W2@W3)
static constexpr int SM_B1   = 7248;                // 50 f32
static constexpr int SM_EP   = 7456;                // 16 f32
static constexpr int SM_FLAG = 7520;                // 1 int (last-block flag)
static constexpr int SM_A    = 7552;                // 208*432 = 89856
static constexpr int SM_ZH   = SM_A  + 208 * STRA;  // 97408:  56*432 = 24192
static constexpr int SM_ZL   = SM_ZH + 56 * STRA;   // 121600: 56*432 = 24192
static constexpr int SM_D    = SM_ZL + 56 * STRA;   // 145792: 208*228 = 47424
static constexpr int SM_TOTAL= SM_D  + 208 * STRD;  // 193216 bytes

__device__ float g_e[1024];          // per-graph energy
__device__ unsigned int g_ctr = 0;   // last-block counter (reset each launch)

// ---------------------------------------------------------------------------
static __device__ __forceinline__ uint32_t smem_u32(const void* p) {
    uint32_t a;
    asm("{ .reg .u64 t; cvta.to.shared.u64 t, %1; cvt.u32.u64 %0, t; }" : "=r"(a) : "l"(p));
    return a;
}
static __device__ __forceinline__ void ldsm_x4(uint32_t& r0, uint32_t& r1,
                                               uint32_t& r2, uint32_t& r3, uint32_t a) {
    asm volatile("ldmatrix.sync.aligned.m8n8.x4.shared.b16 {%0,%1,%2,%3}, [%4];"
                 : "=r"(r0), "=r"(r1), "=r"(r2), "=r"(r3) : "r"(a));
}
static __device__ __forceinline__ void ldsm_x2(uint32_t& r0, uint32_t& r1, uint32_t a) {
    asm volatile("ldmatrix.sync.aligned.m8n8.x2.shared.b16 {%0,%1}, [%2];"
                 : "=r"(r0), "=r"(r1) : "r"(a));
}
static __device__ __forceinline__ void mma16816(float* c,
                                                uint32_t a0, uint32_t a1, uint32_t a2, uint32_t a3,
                                                uint32_t b0, uint32_t b1) {
    asm volatile("mma.sync.aligned.m16n8k16.row.col.f32.bf16.bf16.f32 "
                 "{%0,%1,%2,%3}, {%4,%5,%6,%7}, {%8,%9}, {%0,%1,%2,%3};"
                 : "+f"(c[0]), "+f"(c[1]), "+f"(c[2]), "+f"(c[3])
                 : "r"(a0), "r"(a1), "r"(a2), "r"(a3), "r"(b0), "r"(b1));
}

// ---------------------------------------------------------------------------
__global__ void __launch_bounds__(THREADS, 1) gnn_main(
    const float* __restrict__ x,   // [R,B,200,5]
    const int*   __restrict__ adj, // [R,B,200,200]
    const float* __restrict__ nu,  // [B,R]
    const float* __restrict__ W1,  // [5,50]
    const float* __restrict__ b1,  // [50]
    const float* __restrict__ W2,  // [50,2]
    const float* __restrict__ b2,  // [2]
    const float* __restrict__ W3,  // [2,1]
    const float* __restrict__ b3,  // [1]
    float* __restrict__ out)       // [B]
{
    extern __shared__ char smem[];
    const uint32_t sb = smem_u32(smem);
    const int tid = threadIdx.x, wid = tid >> 5, lid = tid & 31;
    const int g = blockIdx.x;

    float* dinv_s = (float*)(smem + SM_DINV);
    float* q_s    = (float*)(smem + SM_Q);
    float* x_s    = (float*)(smem + SM_X);
    float* w1_s   = (float*)(smem + SM_W1);
    float* w_s    = (float*)(smem + SM_W);
    float* b1_s   = (float*)(smem + SM_B1);
    float* ep_s   = (float*)(smem + SM_EP);

    // --- Phase 0: targeted pad zeroing (only regions ldsm/epilogue ever read)
    {
        uint4 z; z.x = z.y = z.z = z.w = 0u;
        // A rows 0..199, cols 200..207 (16B @ row*432+400)
        if (tid < 200) *reinterpret_cast<uint4*>(smem + SM_A + tid * STRA + 400) = z;
        // ZH/ZL rows f=0..49, m=200..207
        if (tid < 50) {
            *reinterpret_cast<uint4*>(smem + SM_ZH + tid * STRA + 400) = z;
            *reinterpret_cast<uint4*>(smem + SM_ZL + tid * STRA + 400) = z;
        }
        // A rows 200..207, cols 0..207 (26 uint4/row * 8 rows = 208)
        if (tid < 208) {
            int r = tid / 26, c = tid - r * 26;
            *reinterpret_cast<uint4*>(smem + SM_A + (200 + r) * STRA + c * 16) = z;
        }
        // ZH/ZL rows f=50..55, m=0..207 (26 uint4/row * 6 rows = 156)
        if (tid < 156) {
            int r = tid / 26, c = tid - r * 26;
            *reinterpret_cast<uint4*>(smem + SM_ZH + (50 + r) * STRA + c * 16) = z;
            *reinterpret_cast<uint4*>(smem + SM_ZL + (50 + r) * STRA + c * 16) = z;
        }
    }
    {
        const float* xg = x + (size_t)g * 1000;
        for (int i = tid; i < 1000; i += THREADS) x_s[i] = xg[i];
        if (tid < 250) w1_s[tid] = W1[tid];
        if (tid < 50) {
            w_s[tid]  = W2[tid * 2] * W3[0] + W2[tid * 2 + 1] * W3[1];
            b1_s[tid] = b1[tid];
        }
    }
    // No sync needed yet: Phase 1 writes disjoint smem; sync before first read.

    // --- Phase 1: adjacency -> bf16 rows, front-batched (MLP=10 per thread).
    // Flat: 10000 int4 (4 ints = 4 bf16 = 8 smem bytes). 2 batches of 10x512.
    {
        const int4* ab = reinterpret_cast<const int4*>(adj) + (size_t)g * 10000;
        #pragma unroll 1
        for (int base = 0; base < 10000; base += 5120) {
            int4 v[10];
            #pragma unroll
            for (int i = 0; i < 10; ++i) {
                int idx = base + i * 512 + tid;
                if (idx < 10000) v[i] = ab[idx];
                else             v[i] = make_int4(0, 0, 0, 0);
            }
            #pragma unroll
            for (int i = 0; i < 10; ++i) {
                int idx = base + i * 512 + tid;
                if (idx < 10000) {
                    int row = idx / 50;
                    int c   = idx - row * 50;
                    uint2 p;   // int 0/1 -> packed bf16x2 (0x3F80 = bf16 1.0)
                    p.x = (uint32_t)v[i].x * 0x3F80u + (uint32_t)v[i].y * 0x3F800000u;
                    p.y = (uint32_t)v[i].z * 0x3F80u + (uint32_t)v[i].w * 0x3F800000u;
                    *reinterpret_cast<uint2*>(smem + SM_A + row * STRA + c * 8) = p;
                }
            }
        }
    }
    __syncthreads();

    // --- Phase 2a: self loop on diagonal (A[n,n] += 1; exact {1,2})
    if (tid < 200) {
        __nv_bfloat16* pp = (__nv_bfloat16*)(smem + SM_A + tid * STRA + tid * 2);
        *pp = __float2bfloat16(__bfloat162float(*pp) + 1.0f);
    }
    __syncthreads();

    // --- Phase 2b: deg[n] = rowsum of A (incl. self loop); dinv = rsqrt(deg)
    {
        for (int row = wid; row < 200; row += 16) {
            const uint32_t* Ar = (const uint32_t*)(smem + SM_A + row * STRA);
            float s = 0.f;
            #pragma unroll
            for (int c = 0; c < 3; ++c) {
                uint32_t pr = Ar[c * 32 + lid];
                float2 a2 = __bfloat1622float2(*(const __nv_bfloat162*)&pr);
                s += a2.x + a2.y;
            }
            if (lid < 4) {
                uint32_t pr = Ar[96 + lid];
                float2 a2 = __bfloat1622float2(*(const __nv_bfloat162*)&pr);
                s += a2.x + a2.y;
            }
            #pragma unroll
            for (int o = 16; o > 0; o >>= 1) s += __shfl_down_sync(0xFFFFFFFFu, s, o);
            if (lid == 0) dinv_s[row] = rsqrtf(s);
        }
    }
    __syncthreads();

    // --- Phase 3: zd^T hi/lo bf16 into [f][m] rows (stride 432B)
    for (int idx = tid; idx < 5000; idx += THREADS) {
        int f  = idx / 100;
        int mp = idx - f * 100;
        int m0 = mp * 2;
        const float* xr = x_s + m0 * 5;
        float z0 = 0.f, z1 = 0.f;
        #pragma unroll
        for (int k = 0; k < 5; k++) {
            float wv = w1_s[k * 50 + f];
            z0 += xr[k] * wv;
            z1 += xr[5 + k] * wv;
        }
        z0 *= dinv_s[m0];
        z1 *= dinv_s[m0 + 1];
        __nv_bfloat16 h0 = __float2bfloat16(z0);
        __nv_bfloat16 h1 = __float2bfloat16(z1);
        __nv_bfloat16 l0 = __float2bfloat16(z0 - __bfloat162float(h0));
        __nv_bfloat16 l1 = __float2bfloat16(z1 - __bfloat162float(h1));
        uint32_t hp = (uint32_t)__bfloat16_as_ushort(h0) | ((uint32_t)__bfloat16_as_ushort(h1) << 16);
        uint32_t lp = (uint32_t)__bfloat16_as_ushort(l0) | ((uint32_t)__bfloat16_as_ushort(l1) << 16);
        uint32_t off = (uint32_t)f * STRA + (uint32_t)m0 * 2;
        *(uint32_t*)(smem + SM_ZH + off) = hp;
        *(uint32_t*)(smem + SM_ZL + off) = lp;
    }
    __syncthreads();

    // --- Phase 4: D = A @ zd via mma.sync. 13 M-tiles x 7 N-tiles.
    // One M-tile per warp (warps 13..15 idle here).
    if (wid < 13) {
        const uint32_t a_lane = sb + SM_A + (uint32_t)(lid & 15) * STRA + (uint32_t)(lid >> 4) * 16;
        const uint32_t b_lane = (uint32_t)(lid & 7) * STRA + (uint32_t)((lid >> 3) & 1) * 16;

        float acc[7][4];
        #pragma unroll
        for (int nt = 0; nt < 7; nt++)
            #pragma unroll
            for (int i = 0; i < 4; i++) acc[nt][i] = 0.f;

        for (int k = 0; k < 13; ++k) {
            uint32_t a0, a1, a2, a3;
            ldsm_x4(a0, a1, a2, a3, a_lane + (uint32_t)(wid * 16) * STRA + (uint32_t)k * 32);
            uint32_t bh[7][2], bl[7][2];
            #pragma unroll
            for (int nt = 0; nt < 7; ++nt) {
                uint32_t ba = sb + SM_ZH + (uint32_t)(nt * 8) * STRA + (uint32_t)k * 32 + b_lane;
                ldsm_x2(bh[nt][0], bh[nt][1], ba);
                ldsm_x2(bl[nt][0], bl[nt][1], ba + (SM_ZL - SM_ZH));
            }
            #pragma unroll
            for (int nt = 0; nt < 7; ++nt) {
                mma16816(acc[nt], a0, a1, a2, a3, bh[nt][0], bh[nt][1]);
                mma16816(acc[nt], a0, a1, a2, a3, bl[nt][0], bl[nt][1]);
            }
        }

        // store C fragments to D. STRD = 228 B is 4-mod-8 -> scalar stores only.
        #pragma unroll
        for (int nt = 0; nt < 7; ++nt) {
            uint32_t r0 = (uint32_t)(wid * 16 + (lid >> 2));
            uint32_t c4 = (uint32_t)(nt * 8 + (lid & 3) * 2) * 4;
            uint32_t ad0 = sb + SM_D + r0 * STRD + c4;
            asm volatile("st.shared.f32 [%0], %1;"
                         :: "r"(ad0), "f"(acc[nt][0]) : "memory");
            asm volatile("st.shared.f32 [%0], %1;"
                         :: "r"(ad0 + 4u), "f"(acc[nt][1]) : "memory");
            asm volatile("st.shared.f32 [%0], %1;"
                         :: "r"(ad0 + 8u * STRD), "f"(acc[nt][2]) : "memory");
            asm volatile("st.shared.f32 [%0], %1;"
                         :: "r"(ad0 + 8u * STRD + 4u), "f"(acc[nt][3]) : "memory");
        }
    }
    __syncthreads();

    // --- Phase 5: per-atom silu + dot(w); q[n] = dinv[n]*p[n] (0 for pads)
    if (tid < 256) {
        int n = tid;
        float qv = 0.f;
        if (n < 200) {
            float dn = dinv_s[n];
            const float* Dr = (const float*)(smem + SM_D + n * STRD);
            float p = 0.f;
            #pragma unroll
            for (int f = 0; f < 50; ++f) {
                float h = dn * Dr[f] + b1_s[f];
                p += (h / (1.0f + __expf(-h))) * w_s[f];
            }
            qv = dn * p;
        }
        q_s[n] = qv;
    }
    __syncthreads();

    // --- Phase 6: e = sum_n dinv[n] * (A[n,:] . q)
    {
        float my = 0.f;
        for (int n = wid; n < 200; n += 16) {
            const char* Ar = smem + SM_A + n * STRA;
            float acc2 = 0.f;
            #pragma unroll
            for (int c = 0; c < 3; ++c) {       // m = 0..191
                uint32_t pr = *(const uint32_t*)(Ar + c * 128 + lid * 4);
                float2 a2 = __bfloat1622float2(*(const __nv_bfloat162*)&pr);
                float2 qq = *(const float2*)(smem + SM_Q + (c * 64 + lid * 2) * 4);
                acc2 += a2.x * qq.x + a2.y * qq.y;
            }
            if (lid < 8) {                       // m = 192..207 (pads zero)
                uint32_t pr = *(const uint32_t*)(Ar + 384 + lid * 4);
                float2 a2 = __bfloat1622float2(*(const __nv_bfloat162*)&pr);
                float2 qq = *(const float2*)(smem + SM_Q + (192 + lid * 2) * 4);
                acc2 += a2.x * qq.x + a2.y * qq.y;
            }
            #pragma unroll
            for (int o = 16; o > 0; o >>= 1) acc2 += __shfl_down_sync(0xFFFFFFFFu, acc2, o);
            if (lid == 0) my += dinv_s[n] * acc2;
        }
        if (lid == 0) ep_s[wid] = my;
    }
    __syncthreads();

    // --- Tail: publish e; last block does the deterministic combine.
    if (tid == 0) {
        float e = 0.f;
        #pragma unroll
        for (int i = 0; i < 16; i++) e += ep_s[i];
        g_e[g] = e;
        __threadfence();
        unsigned v = atomicAdd(&g_ctr, 1u);
        *(int*)(smem + SM_FLAG) = (v == (unsigned)(gridDim.x - 1)) ? 1 : 0;
    }
    __syncthreads();
    if (*(int*)(smem + SM_FLAG)) {
        if (tid == 0) g_ctr = 0;                 // reset for next graph replay
        if (tid < 256) {
            volatile const float* ge = g_e;      // peers' writes are L2-visible
            float s3 = b2[0] * W3[0] + b2[1] * W3[1] + b3[0];
            float bias = 200.0f * s3;
            int b = tid;
            float acc = 0.f;
            #pragma unroll
            for (int r = 0; r < 4; r++)
                acc += nu[b * 4 + r] * (ge[r * 256 + b] + bias);
            out[b] = acc;
        }
    }
}

// ---------------------------------------------------------------------------
extern "C" void kernel_launch(void* const* d_in, const int* in_sizes, int n_in,
                              void* d_out, int out_size) {
    const float* x   = (const float*)d_in[0];
    const int*   adj = (const int*)  d_in[1];
    const float* nu  = (const float*)d_in[2];
    const float* W1  = (const float*)d_in[3];
    const float* b1  = (const float*)d_in[4];
    const float* W2  = (const float*)d_in[5];
    const float* b2  = (const float*)d_in[6];
    const float* W3  = (const float*)d_in[7];
    const float* b3  = (const float*)d_in[8];

    cudaFuncSetAttribute(gnn_main, cudaFuncAttributeMaxDynamicSharedMemorySize, SM_TOTAL);

    gnn_main<<<1024, THREADS, SM_TOTAL>>>(x, adj, nu, W1, b1, W2, b2, W3, b3,
                                          (float*)d_out);
}